// round 7
// baseline (speedup 1.0000x reference)
#include <cuda_runtime.h>
#include <cstdint>

#define BB 512
#define TT 2000
#define HH 50
#define CH 32
#define HSTRIDE 68          // floats per hist row, rows 16B-aligned (68*4=272)
#define HIST_FLOATS (33 * HSTRIDE)          // per batch-slot
#define XS_FLOATS   (2 * 96)                // per batch-slot (double-buffered 96)
#define DSM_HIST_TOTAL (8 * HIST_FLOATS)    // 17952 floats
#define DSM_TOTAL_BYTES ((DSM_HIST_TOTAL + 8 * XS_FLOATS) * 4)   // 77,952 B

typedef unsigned long long ull;

__device__ __forceinline__ ull packf2(float a, float b) {
    ull r;
    asm("mov.b64 %0, {%1, %2};" : "=l"(r) : "f"(a), "f"(b));
    return r;
}
__device__ __forceinline__ void unpackf2(ull v, float& lo, float& hi) {
    asm("mov.b64 {%0, %1}, %2;" : "=f"(lo), "=f"(hi) : "l"(v));
}
#define FMA2(acc, a, b) \
    asm("fma.rn.f32x2 %0, %1, %2, %0;" : "+l"(acc) : "l"(a), "l"(b))
#define ADD2(dst, a, b) \
    asm("add.rn.f32x2 %0, %1, %2;" : "=l"(dst) : "l"(a), "l"(b))
#define CP_ASYNC16(dst_u32, src) \
    asm volatile("cp.async.ca.shared.global [%0], [%1], 16;" :: "r"(dst_u32), "l"(src))
#define CP_COMMIT() asm volatile("cp.async.commit_group;")
#define CP_WAIT0()  asm volatile("cp.async.wait_group 0;")

__global__ __launch_bounds__(128, 1)
void rnn_kernel(const float* __restrict__ x,
                const float* __restrict__ W_ih,
                const float* __restrict__ W_hh,
                const float* __restrict__ b_ih,
                const float* __restrict__ b_hh,
                const float* __restrict__ W_out,
                const float* __restrict__ b_out,
                float* __restrict__ y)
{
    extern __shared__ __align__(16) float dsm[];
    __shared__ ull  wosh[3][25];
    __shared__ float bosh[3];

    const int tid  = threadIdx.x;
    const int warp = tid >> 5;
    const int lane = tid & 31;
    // two batches per warp
    const int qA = warp * 2;
    const int qB = warp * 2 + 1;
    const int bA = blockIdx.x * 8 + qA;
    const int bB = blockIdx.x * 8 + qB;

    if (tid < 75) {
        const int d = tid / 25, q = tid % 25;
        wosh[d][q] = packf2(W_out[d * HH + 2 * q], W_out[d * HH + 2 * q + 1]);
    }
    if (tid < 3) bosh[tid] = b_out[tid];

    const int j0 = lane;
    const int j1 = lane + 32;
    const bool j1v = (j1 < HH);

    // shared-across-batches weights (per-lane rows of W_hh)
    ull w0[25], w1[25];
#pragma unroll
    for (int q = 0; q < 25; q++) {
        w0[q] = packf2(W_hh[j0 * HH + 2 * q], W_hh[j0 * HH + 2 * q + 1]);
        w1[q] = j1v ? packf2(W_hh[j1 * HH + 2 * q], W_hh[j1 * HH + 2 * q + 1]) : 0ull;
    }
    const float wi0a = W_ih[j0 * 3 + 0], wi0b = W_ih[j0 * 3 + 1], wi0c = W_ih[j0 * 3 + 2];
    const float bias0 = b_ih[j0] + b_hh[j0];
    const float wi1a = j1v ? W_ih[j1 * 3 + 0] : 0.f;
    const float wi1b = j1v ? W_ih[j1 * 3 + 1] : 0.f;
    const float wi1c = j1v ? W_ih[j1 * 3 + 2] : 0.f;
    const float bias1 = j1v ? (b_ih[j1] + b_hh[j1]) : 0.f;

    float* const hA = dsm + qA * HIST_FLOATS;
    float* const hB = dsm + qB * HIST_FLOATS;
    float* const xsA = dsm + DSM_HIST_TOTAL + qA * XS_FLOATS;
    float* const xsB = dsm + DSM_HIST_TOTAL + qB * XS_FLOATS;

    // h_{-1} = 0 in row 0 (cols 50..63 rewritten as 0 each step)
    hA[lane] = 0.f; hA[lane + 32] = 0.f;
    hB[lane] = 0.f; hB[lane + 32] = 0.f;

    const float* __restrict__ xbA = x + (size_t)bA * TT * 3;
    const float* __restrict__ xbB = x + (size_t)bB * TT * 3;
    float* __restrict__ ybA = y + (size_t)bA * TT * 3;
    float* __restrict__ ybB = y + (size_t)bB * TT * 3;

    const uint32_t xsA0 = (uint32_t)__cvta_generic_to_shared(xsA);
    const uint32_t xsA1 = xsA0 + 96 * 4;
    const uint32_t xsB0 = (uint32_t)__cvta_generic_to_shared(xsB);
    const uint32_t xsB1 = xsB0 + 96 * 4;

    // stage x chunk 0 for both batches
    if (lane < 24) {
        CP_ASYNC16(xsA0 + lane * 16, xbA + lane * 4);
        CP_ASYNC16(xsB0 + lane * 16, xbB + lane * 4);
    }
    CP_COMMIT();
    CP_WAIT0();
    __syncthreads();   // wosh/bosh + staged x visibility (outside hot loop)

    int buf = 0;
    for (int base = 0; base < TT; base += CH) {
        const int cnt = min(CH, TT - base);     // 32 or 16

        // prefetch next chunk's x into the other buffers
        {
            const int ncnt = min(CH, TT - base - CH);
            if (base + CH < TT && lane * 16 < ncnt * 12) {
                CP_ASYNC16((buf ? xsA0 : xsA1) + lane * 16, xbA + (size_t)(base + CH) * 3 + lane * 4);
                CP_ASYNC16((buf ? xsB0 : xsB1) + lane * 16, xbB + (size_t)(base + CH) * 3 + lane * 4);
            }
            CP_COMMIT();
        }

        const float* __restrict__ xpA = xsA + buf * 96;
        const float* __restrict__ xpB = xsB + buf * 96;

        // ---- recurrence: 2 interleaved independent batches, no syncs ----
        for (int g = 0; g < cnt; g += 4) {
#pragma unroll
            for (int u = 0; u < 4; u++) {
                const int s = g + u;
                const float xA0 = xpA[3 * s + 0], xA1 = xpA[3 * s + 1], xA2 = xpA[3 * s + 2];
                const float xB0 = xpB[3 * s + 0], xB1 = xpB[3 * s + 1], xB2 = xpB[3 * s + 2];
                const float xhA0 = fmaf(xA2, wi0c, fmaf(xA1, wi0b, fmaf(xA0, wi0a, bias0)));
                const float xhA1 = fmaf(xA2, wi1c, fmaf(xA1, wi1b, fmaf(xA0, wi1a, bias1)));
                const float xhB0 = fmaf(xB2, wi0c, fmaf(xB1, wi0b, fmaf(xB0, wi0a, bias0)));
                const float xhB1 = fmaf(xB2, wi1c, fmaf(xB1, wi1b, fmaf(xB0, wi1a, bias1)));

                const float* hrA = hA + s * HSTRIDE;
                const float* hrB = hB + s * HSTRIDE;
                ull aA0 = packf2(xhA0, 0.f), aA1 = 0ull;
                ull cA0 = packf2(xhA1, 0.f), cA1 = 0ull;
                ull aB0 = packf2(xhB0, 0.f), aB1 = 0ull;
                ull cB0 = packf2(xhB1, 0.f), cB1 = 0ull;
#pragma unroll
                for (int p = 0; p < 12; p++) {
                    const ulonglong2 hvA = *reinterpret_cast<const ulonglong2*>(hrA + 4 * p);
                    const ulonglong2 hvB = *reinterpret_cast<const ulonglong2*>(hrB + 4 * p);
                    FMA2(aA0, hvA.x, w0[2 * p]);
                    FMA2(aB0, hvB.x, w0[2 * p]);
                    FMA2(cA0, hvA.x, w1[2 * p]);
                    FMA2(cB0, hvB.x, w1[2 * p]);
                    FMA2(aA1, hvA.y, w0[2 * p + 1]);
                    FMA2(aB1, hvB.y, w0[2 * p + 1]);
                    FMA2(cA1, hvA.y, w1[2 * p + 1]);
                    FMA2(cB1, hvB.y, w1[2 * p + 1]);
                }
                const ull hlA = *reinterpret_cast<const ull*>(hrA + 48);
                const ull hlB = *reinterpret_cast<const ull*>(hrB + 48);
                FMA2(aA0, hlA, w0[24]);
                FMA2(aB0, hlB, w0[24]);
                FMA2(cA0, hlA, w1[24]);
                FMA2(cB0, hlB, w1[24]);

                ull sA0, sA1, sB0, sB1;
                ADD2(sA0, aA0, aA1); ADD2(sA1, cA0, cA1);
                ADD2(sB0, aB0, aB1); ADD2(sB1, cB0, cB1);
                float lA0, uA0, lA1, uA1, lB0, uB0, lB1, uB1;
                unpackf2(sA0, lA0, uA0);
                unpackf2(sA1, lA1, uA1);
                unpackf2(sB0, lB0, uB0);
                unpackf2(sB1, lB1, uB1);
                const float hA0 = fmaxf(lA0 + uA0, 0.f);
                const float hA1 = fmaxf(lA1 + uA1, 0.f);
                const float hB0 = fmaxf(lB0 + uB0, 0.f);
                const float hB1 = fmaxf(lB1 + uB1, 0.f);

                float* hwA = hA + (s + 1) * HSTRIDE;
                float* hwB = hB + (s + 1) * HSTRIDE;
                hwA[lane] = hA0; hwA[lane + 32] = hA1;
                hwB[lane] = hB0; hwB[lane + 32] = hB1;
            }
        }

        // carry last row -> row 0 (same-warp, in-order smem)
        hA[lane] = hA[cnt * HSTRIDE + lane];
        hA[lane + 32] = hA[cnt * HSTRIDE + lane + 32];
        hB[lane] = hB[cnt * HSTRIDE + lane];
        hB[lane + 32] = hB[cnt * HSTRIDE + lane + 32];

        // ---- chunk projections (lane s -> timestep base+s, row s+1) ----
        if (lane < cnt) {
#pragma unroll
            for (int which = 0; which < 2; which++) {
                const float* pr = (which ? hB : hA) + (lane + 1) * HSTRIDE;
                float* yo = (which ? ybB : ybA) + (size_t)(base + lane) * 3;
                ull a0 = 0ull, c0 = 0ull, a1 = 0ull, c1 = 0ull, a2 = 0ull, c2 = 0ull;
#pragma unroll
                for (int p = 0; p < 12; p++) {
                    const ulonglong2 hv = *reinterpret_cast<const ulonglong2*>(pr + 4 * p);
                    FMA2(a0, hv.x, wosh[0][2 * p]); FMA2(c0, hv.y, wosh[0][2 * p + 1]);
                    FMA2(a1, hv.x, wosh[1][2 * p]); FMA2(c1, hv.y, wosh[1][2 * p + 1]);
                    FMA2(a2, hv.x, wosh[2][2 * p]); FMA2(c2, hv.y, wosh[2][2 * p + 1]);
                }
                const ull hl = *reinterpret_cast<const ull*>(pr + 48);
                FMA2(a0, hl, wosh[0][24]);
                FMA2(a1, hl, wosh[1][24]);
                FMA2(a2, hl, wosh[2][24]);

                ull s0, s1, s2;
                ADD2(s0, a0, c0); ADD2(s1, a1, c1); ADD2(s2, a2, c2);
                float p0l, p0h, p1l, p1h, p2l, p2h;
                unpackf2(s0, p0l, p0h);
                unpackf2(s1, p1l, p1h);
                unpackf2(s2, p2l, p2h);
                yo[0] = p0l + p0h + bosh[0];
                yo[1] = p1l + p1h + bosh[1];
                yo[2] = p2l + p2h + bosh[2];
            }
        }

        CP_WAIT0();
        __syncwarp();
        buf ^= 1;
    }
}

extern "C" void kernel_launch(void* const* d_in, const int* in_sizes, int n_in,
                              void* d_out, int out_size) {
    const float* x     = (const float*)d_in[0];
    const float* W_ih  = (const float*)d_in[1];
    const float* W_hh  = (const float*)d_in[2];
    const float* b_ih  = (const float*)d_in[3];
    const float* b_hh  = (const float*)d_in[4];
    const float* W_out = (const float*)d_in[5];
    const float* b_out = (const float*)d_in[6];
    float* y = (float*)d_out;

    cudaFuncSetAttribute(rnn_kernel, cudaFuncAttributeMaxDynamicSharedMemorySize,
                         DSM_TOTAL_BYTES);
    rnn_kernel<<<BB / 8, 128, DSM_TOTAL_BYTES>>>(x, W_ih, W_hh, b_ih, b_hh, W_out, b_out, y);
}